// round 2
// baseline (speedup 1.0000x reference)
#include <cuda_runtime.h>
#include <math.h>

// ---------------- problem constants ----------------
static constexpr int B_   = 4;
static constexpr int NTOK = 1569;
static constexpr int C_   = 768;
static constexpr int H_   = 12;
static constexpr int D_   = 64;
static constexpr int F_   = 9;            // CLS + 8 temporal tokens
static constexpr int BN   = B_ * NTOK;    // 6276
static constexpr int C3   = 3 * C_;       // 2304
static constexpr int DFF  = 4 * C_;       // 3072

// ---------------- scratch (static device globals; no allocs) ----------------
__device__ __align__(16) float g_h[BN * C_];          // LN output (reused for h2)
__device__ __align__(16) float g_qkv[BN * C3];        // qkv projection
__device__ __align__(16) float g_attn[BN * C_];       // attention output pre-proj
__device__ __align__(16) float g_out[BN * C_];        // proj output ("new x")
__device__ __align__(16) float g_m[BN * DFF];         // fc1 output (post-GELU)

// device-side scratch selection (avoids any host-side symbol-address API)
template <int WHICH> __device__ __forceinline__ float* scratch();
template <> __device__ __forceinline__ float* scratch<0>() { return g_h;    }
template <> __device__ __forceinline__ float* scratch<1>() { return g_qkv;  }
template <> __device__ __forceinline__ float* scratch<2>() { return g_attn; }
template <> __device__ __forceinline__ float* scratch<3>() { return g_out;  }
template <> __device__ __forceinline__ float* scratch<4>() { return g_m;    }

// ---------------- LayerNorm: one block per row; writes g_h ----------------
// IN: 0 -> external pointer (x), 3 -> g_out
template <int INBUF>
__global__ void __launch_bounds__(256) ln_kernel(const float* __restrict__ ext_in,
                                                 const float* __restrict__ gam,
                                                 const float* __restrict__ bet) {
    const float* in = (INBUF < 0) ? ext_in : scratch<(INBUF < 0) ? 0 : INBUF>();
    int row = blockIdx.x;
    const float* x = in + (size_t)row * C_;
    int tid = threadIdx.x;
    float v0 = x[tid], v1 = x[tid + 256], v2 = x[tid + 512];
    float s  = v0 + v1 + v2;
    float ss = v0 * v0 + v1 * v1 + v2 * v2;
#pragma unroll
    for (int off = 16; off; off >>= 1) {
        s  += __shfl_xor_sync(0xffffffffu, s, off);
        ss += __shfl_xor_sync(0xffffffffu, ss, off);
    }
    __shared__ float sm[8], sm2[8], stats[2];
    int warp = tid >> 5, lane = tid & 31;
    if (lane == 0) { sm[warp] = s; sm2[warp] = ss; }
    __syncthreads();
    if (tid == 0) {
        float S = 0.f, SS = 0.f;
#pragma unroll
        for (int w = 0; w < 8; w++) { S += sm[w]; SS += sm2[w]; }
        float mean = S * (1.0f / C_);
        float var  = SS * (1.0f / C_) - mean * mean;
        stats[0] = mean;
        stats[1] = rsqrtf(var + 1e-5f);
    }
    __syncthreads();
    float mean = stats[0], rstd = stats[1];
    float* o = g_h + (size_t)row * C_;
    o[tid]       = (v0 - mean) * rstd * gam[tid]       + bet[tid];
    o[tid + 256] = (v1 - mean) * rstd * gam[tid + 256] + bet[tid + 256];
    o[tid + 512] = (v2 - mean) * rstd * gam[tid + 512] + bet[tid + 512];
}

// ---------------- GEMM: C[M,Nn] = A[M,K] * W[Nn,K]^T (+epilogue) ----------------
// EPI: 0 = none, 1 = +bias, 2 = +bias then exact GELU, 3 = +bias +residual(g_out)
// ABUF selects A scratch; OBUF selects output scratch, or -1 -> external out.
template <int EPI, int ABUF, int OBUF>
__global__ void __launch_bounds__(256) gemm_tn(const float* __restrict__ W,
                                               const float* __restrict__ bias,
                                               float* __restrict__ ext_out,
                                               int M, int Nn, int K) {
    const float* A = scratch<ABUF>();
    float* Co = (OBUF < 0) ? ext_out : scratch<(OBUF < 0) ? 0 : OBUF>();

    __shared__ float As[16][128];
    __shared__ float Bs[16][128];

    int n0 = blockIdx.x * 128;
    int m0 = blockIdx.y * 128;
    int tid = threadIdx.x;
    int row0 = (tid / 16) * 8;
    int col0 = (tid % 16) * 8;

    float acc[8][8];
#pragma unroll
    for (int i = 0; i < 8; i++)
#pragma unroll
        for (int j = 0; j < 8; j++) acc[i][j] = 0.f;

    for (int k0 = 0; k0 < K; k0 += 16) {
#pragma unroll
        for (int it = 0; it < 2; it++) {
            int idx = tid + it * 256;     // 0..511
            int r   = idx >> 2;           // 0..127
            int kk  = (idx & 3) * 4;      // 0,4,8,12
            int gr  = m0 + r;
            float4 va;
            if (gr < M) va = *(const float4*)(A + (size_t)gr * K + k0 + kk);
            else        va = make_float4(0.f, 0.f, 0.f, 0.f);
            As[kk + 0][r] = va.x; As[kk + 1][r] = va.y;
            As[kk + 2][r] = va.z; As[kk + 3][r] = va.w;
            // Nn is always a multiple of 128 here -> no guard
            float4 vb = *(const float4*)(W + (size_t)(n0 + r) * K + k0 + kk);
            Bs[kk + 0][r] = vb.x; Bs[kk + 1][r] = vb.y;
            Bs[kk + 2][r] = vb.z; Bs[kk + 3][r] = vb.w;
        }
        __syncthreads();
#pragma unroll
        for (int kk = 0; kk < 16; kk++) {
            float4 a0 = *(const float4*)&As[kk][row0];
            float4 a1 = *(const float4*)&As[kk][row0 + 4];
            float4 b0 = *(const float4*)&Bs[kk][col0];
            float4 b1 = *(const float4*)&Bs[kk][col0 + 4];
            float av[8] = {a0.x, a0.y, a0.z, a0.w, a1.x, a1.y, a1.z, a1.w};
            float bv[8] = {b0.x, b0.y, b0.z, b0.w, b1.x, b1.y, b1.z, b1.w};
#pragma unroll
            for (int i = 0; i < 8; i++)
#pragma unroll
                for (int j = 0; j < 8; j++) acc[i][j] += av[i] * bv[j];
        }
        __syncthreads();
    }

#pragma unroll
    for (int i = 0; i < 8; i++) {
        int gr = m0 + row0 + i;
        if (gr >= M) continue;
#pragma unroll
        for (int j = 0; j < 8; j++) {
            int gc = n0 + col0 + j;
            float v = acc[i][j];
            if (EPI >= 1) v += bias[gc];
            if (EPI == 2) v = 0.5f * v * (1.0f + erff(v * 0.70710678f));
            if (EPI == 3) v += g_out[(size_t)gr * Nn + gc];
            Co[(size_t)gr * Nn + gc] = v;
        }
    }
}

// ---------------- attention, spatial rows (i >= F): 9 keys each ----------------
// block = 256 threads = 8 warps; each warp handles one row; K/V(9x64) in smem.
__global__ void __launch_bounds__(256) attn_spatial() {
    const float* qkv = g_qkv;
    const int CH = (NTOK - F_) / 8;     // 195
    int bid   = blockIdx.x;
    int chunk = bid % CH;
    int bh    = bid / CH;
    int h     = bh % H_;
    int b     = bh / H_;

    __shared__ float ks[F_][D_], vs[F_][D_];
    int tid = threadIdx.x;
    for (int idx = tid; idx < F_ * D_; idx += 256) {
        int j = idx / D_, dd = idx % D_;
        const float* base = qkv + ((size_t)(b * NTOK + j)) * C3 + h * D_;
        ks[j][dd] = base[C_ + dd];
        vs[j][dd] = base[2 * C_ + dd];
    }
    __syncthreads();

    int warp = tid >> 5, lane = tid & 31;
    int i = F_ + chunk * 8 + warp;       // always < NTOK (1560 divisible by 8)
    const float* q = qkv + ((size_t)(b * NTOK + i)) * C3 + h * D_;
    float q0 = q[lane], q1 = q[lane + 32];

    float lg[F_];
#pragma unroll
    for (int j = 0; j < F_; j++) {
        float p = q0 * ks[j][lane] + q1 * ks[j][lane + 32];
#pragma unroll
        for (int off = 16; off; off >>= 1) p += __shfl_xor_sync(0xffffffffu, p, off);
        lg[j] = p * 0.125f;              // scale = d^-0.5
    }
    float m = lg[0];
#pragma unroll
    for (int j = 1; j < F_; j++) m = fmaxf(m, lg[j]);
    float s = 0.f, a0 = 0.f, a1 = 0.f;
#pragma unroll
    for (int j = 0; j < F_; j++) {
        float w = expf(lg[j] - m);
        s += w;
        a0 += w * vs[j][lane];
        a1 += w * vs[j][lane + 32];
    }
    float inv = 1.0f / s;
    float* o = g_attn + ((size_t)(b * NTOK + i)) * C_ + h * D_;
    o[lane]      = a0 * inv;
    o[lane + 32] = a1 * inv;
}

// ---------------- attention, temporal rows (i < F): ~1560 keys each ----------------
// one block (8 warps) per (b,h,i); two-pass softmax, warp-strided keys.
__global__ void __launch_bounds__(256) attn_temporal() {
    const float* qkv = g_qkv;
    int t = blockIdx.x;                 // 0 .. B*H*F-1
    int i = t % F_;
    int h = (t / F_) % H_;
    int b = t / (F_ * H_);

    __shared__ float qsh[D_];
    __shared__ float wm[8], ws[8];
    __shared__ float accs[8][D_];

    int tid = threadIdx.x, warp = tid >> 5, lane = tid & 31;
    const float* q = qkv + ((size_t)(b * NTOK + i)) * C3 + h * D_;
    if (tid < D_) qsh[tid] = q[tid];
    __syncthreads();
    float q0 = qsh[lane], q1 = qsh[lane + 32];

    int cnt = (NTOK - F_) + (i == 0 ? 1 : 0);

    // pass 1: online max / expsum per warp
    float mloc = -1e30f, sloc = 0.0f;
    for (int tt = warp; tt < cnt; tt += 8) {
        int j = (i == 0) ? ((tt == 0) ? 0 : (F_ - 1 + tt)) : (F_ + tt);
        const float* kp = qkv + ((size_t)(b * NTOK + j)) * C3 + C_ + h * D_;
        float p = q0 * kp[lane] + q1 * kp[lane + 32];
#pragma unroll
        for (int off = 16; off; off >>= 1) p += __shfl_xor_sync(0xffffffffu, p, off);
        float lg = p * 0.125f;
        if (lg > mloc) { sloc *= expf(mloc - lg); mloc = lg; }
        sloc += expf(lg - mloc);
    }
    if (lane == 0) { wm[warp] = mloc; ws[warp] = sloc; }
    __syncthreads();
    float M = wm[0];
#pragma unroll
    for (int w = 1; w < 8; w++) M = fmaxf(M, wm[w]);
    float S = 0.f;
#pragma unroll
    for (int w = 0; w < 8; w++) S += ws[w] * expf(wm[w] - M);

    // pass 2: weighted V accumulation
    float a0 = 0.f, a1 = 0.f;
    for (int tt = warp; tt < cnt; tt += 8) {
        int j = (i == 0) ? ((tt == 0) ? 0 : (F_ - 1 + tt)) : (F_ + tt);
        const float* kp = qkv + ((size_t)(b * NTOK + j)) * C3 + C_ + h * D_;
        float p = q0 * kp[lane] + q1 * kp[lane + 32];
#pragma unroll
        for (int off = 16; off; off >>= 1) p += __shfl_xor_sync(0xffffffffu, p, off);
        float w8 = expf(p * 0.125f - M);
        const float* vp = qkv + ((size_t)(b * NTOK + j)) * C3 + 2 * C_ + h * D_;
        a0 += w8 * vp[lane];
        a1 += w8 * vp[lane + 32];
    }
    accs[warp][lane]      = a0;
    accs[warp][lane + 32] = a1;
    __syncthreads();
    if (tid < D_) {
        float acc = 0.f;
#pragma unroll
        for (int w = 0; w < 8; w++) acc += accs[w][tid];
        g_attn[((size_t)(b * NTOK + i)) * C_ + h * D_ + tid] = acc / S;
    }
}

// ---------------- launch (kernel launches ONLY — fully graph-capturable) ----------------
extern "C" void kernel_launch(void* const* d_in, const int* in_sizes, int n_in,
                              void* d_out, int out_size) {
    const float* x     = (const float*)d_in[0];
    const float* ln_g  = (const float*)d_in[1];
    const float* ln_b  = (const float*)d_in[2];
    const float* qkvw  = (const float*)d_in[3];
    const float* projw = (const float*)d_in[4];
    const float* projb = (const float*)d_in[5];
    const float* fc1w  = (const float*)d_in[6];
    const float* fc1b  = (const float*)d_in[7];
    const float* fc2w  = (const float*)d_in[8];
    const float* fc2b  = (const float*)d_in[9];
    float* out = (float*)d_out;

    // 1. g_h = LN(x)
    ln_kernel<-1><<<BN, 256>>>(x, ln_g, ln_b);

    // 2. g_qkv = g_h @ qkv_w^T
    {
        dim3 grid(C3 / 128, (BN + 127) / 128);
        gemm_tn<0, 0, 1><<<grid, 256>>>(qkvw, nullptr, nullptr, BN, C3, C_);
    }

    // 3. masked attention (sparsity-exploiting) -> g_attn
    attn_spatial<<<B_ * H_ * ((NTOK - F_) / 8), 256>>>();
    attn_temporal<<<B_ * H_ * F_, 256>>>();

    // 4. g_out = g_attn @ proj_w^T + proj_b   (the new "x")
    {
        dim3 grid(C_ / 128, (BN + 127) / 128);
        gemm_tn<1, 2, 3><<<grid, 256>>>(projw, projb, nullptr, BN, C_, C_);
    }

    // 5. g_h = LN(g_out)
    ln_kernel<3><<<BN, 256>>>(nullptr, ln_g, ln_b);

    // 6. g_m = GELU(g_h @ fc1_w^T + fc1_b)
    {
        dim3 grid(DFF / 128, (BN + 127) / 128);
        gemm_tn<2, 0, 4><<<grid, 256>>>(fc1w, fc1b, nullptr, BN, DFF, C_);
    }

    // 7. d_out = g_out + g_m @ fc2_w^T + fc2_b
    {
        dim3 grid(C_ / 128, (BN + 127) / 128);
        gemm_tn<3, 4, -1><<<grid, 256>>>(fc2w, fc2b, out, BN, C_, DFF);
    }
}

// round 5
// speedup vs baseline: 2.8520x; 2.8520x over previous
#include <cuda_runtime.h>
#include <cuda_bf16.h>
#include <math.h>
#include <stdint.h>

// ---------------- problem constants ----------------
static constexpr int B_   = 4;
static constexpr int NTOK = 1569;
static constexpr int C_   = 768;
static constexpr int H_   = 12;
static constexpr int D_   = 64;
static constexpr int F_   = 9;            // CLS + 8 temporal tokens
static constexpr int BN   = B_ * NTOK;    // 6276
static constexpr int C3   = 3 * C_;       // 2304
static constexpr int DFF  = 4 * C_;       // 3072
static constexpr int SPLIT = 8;           // temporal-attention key split

// ---------------- scratch (device globals; no allocs) ----------------
__device__ __align__(16) float g_qkv[BN * C3];        // qkv projection (fp32)
__device__ __align__(16) float g_out[BN * C_];        // proj output ("new x", fp32)
__device__ __align__(16) __nv_bfloat16 g_h_hi[BN * C_],  g_h_lo[BN * C_];   // LN out
__device__ __align__(16) __nv_bfloat16 g_at_hi[BN * C_], g_at_lo[BN * C_];  // attn out
__device__ __align__(16) __nv_bfloat16 g_m_hi[BN * DFF], g_m_lo[BN * DFF];  // fc1 out
__device__ __align__(16) __nv_bfloat16 g_wq_hi[C3 * C_], g_wq_lo[C3 * C_];
__device__ __align__(16) __nv_bfloat16 g_wp_hi[C_ * C_], g_wp_lo[C_ * C_];
__device__ __align__(16) __nv_bfloat16 g_w1_hi[DFF * C_], g_w1_lo[DFF * C_];
__device__ __align__(16) __nv_bfloat16 g_w2_hi[C_ * DFF], g_w2_lo[C_ * DFF];
__device__ float g_part[B_ * H_ * F_ * SPLIT * 66];   // split-softmax partials

// ---------------- helpers ----------------
__device__ __forceinline__ uint32_t smem_u32(const void* p) {
    uint32_t a;
    asm("{ .reg .u64 t; cvta.to.shared.u64 t, %1; cvt.u32.u64 %0, t; }" : "=r"(a) : "l"(p));
    return a;
}
__device__ __forceinline__ void cp16(uint32_t dst, const void* src, int sz) {
    asm volatile("cp.async.cg.shared.global [%0], [%1], 16, %2;" :: "r"(dst), "l"(src), "r"(sz) : "memory");
}
__device__ __forceinline__ void cp_commit() { asm volatile("cp.async.commit_group;" ::: "memory"); }
template <int N>
__device__ __forceinline__ void cp_wait() { asm volatile("cp.async.wait_group %0;" :: "n"(N) : "memory"); }

__device__ __forceinline__ void ldm_x4(uint32_t* r, uint32_t addr) {
    asm volatile("ldmatrix.sync.aligned.m8n8.x4.shared.b16 {%0,%1,%2,%3}, [%4];"
                 : "=r"(r[0]), "=r"(r[1]), "=r"(r[2]), "=r"(r[3]) : "r"(addr));
}
__device__ __forceinline__ void mma_bf16(float* d, const uint32_t* a, uint32_t b0, uint32_t b1) {
    asm volatile("mma.sync.aligned.m16n8k16.row.col.f32.bf16.bf16.f32 "
                 "{%0,%1,%2,%3}, {%4,%5,%6,%7}, {%8,%9}, {%0,%1,%2,%3};"
                 : "+f"(d[0]), "+f"(d[1]), "+f"(d[2]), "+f"(d[3])
                 : "r"(a[0]), "r"(a[1]), "r"(a[2]), "r"(a[3]), "r"(b0), "r"(b1));
}

__device__ __forceinline__ void split_bf16(float v, __nv_bfloat16& hi, __nv_bfloat16& lo) {
    hi = __float2bfloat16(v);
    lo = __float2bfloat16(v - __bfloat162float(hi));
}

// ---------------- weight split kernels ----------------
template <int WID>
__global__ void __launch_bounds__(256) cvt_kernel(const float* __restrict__ w, int n) {
    __nv_bfloat16* hi; __nv_bfloat16* lo;
    if constexpr (WID == 0) { hi = g_wq_hi; lo = g_wq_lo; }
    else if constexpr (WID == 1) { hi = g_wp_hi; lo = g_wp_lo; }
    else if constexpr (WID == 2) { hi = g_w1_hi; lo = g_w1_lo; }
    else { hi = g_w2_hi; lo = g_w2_lo; }
    int i = blockIdx.x * 256 + threadIdx.x;
    if (i < n) { __nv_bfloat16 h, l; split_bf16(w[i], h, l); hi[i] = h; lo[i] = l; }
}

// ---------------- LayerNorm -> hi/lo bf16 into g_h ----------------
template <bool FROM_OUT>
__global__ void __launch_bounds__(256) ln_kernel(const float* __restrict__ ext_in,
                                                 const float* __restrict__ gam,
                                                 const float* __restrict__ bet) {
    const float* in = FROM_OUT ? g_out : ext_in;
    int row = blockIdx.x;
    const float* x = in + (size_t)row * C_;
    int tid = threadIdx.x;
    float v0 = x[tid], v1 = x[tid + 256], v2 = x[tid + 512];
    float s  = v0 + v1 + v2;
    float ss = v0 * v0 + v1 * v1 + v2 * v2;
#pragma unroll
    for (int off = 16; off; off >>= 1) {
        s  += __shfl_xor_sync(0xffffffffu, s, off);
        ss += __shfl_xor_sync(0xffffffffu, ss, off);
    }
    __shared__ float sm[8], sm2[8], stats[2];
    int warp = tid >> 5, lane = tid & 31;
    if (lane == 0) { sm[warp] = s; sm2[warp] = ss; }
    __syncthreads();
    if (tid == 0) {
        float S = 0.f, SS = 0.f;
#pragma unroll
        for (int w = 0; w < 8; w++) { S += sm[w]; SS += sm2[w]; }
        float mean = S * (1.0f / C_);
        float var  = SS * (1.0f / C_) - mean * mean;
        stats[0] = mean;
        stats[1] = rsqrtf(var + 1e-5f);
    }
    __syncthreads();
    float mean = stats[0], rstd = stats[1];
    size_t base = (size_t)row * C_;
#pragma unroll
    for (int t = 0; t < 3; t++) {
        int c = tid + t * 256;
        float v = t == 0 ? v0 : (t == 1 ? v1 : v2);
        float y = (v - mean) * rstd * gam[c] + bet[c];
        __nv_bfloat16 h, l; split_bf16(y, h, l);
        g_h_hi[base + c] = h; g_h_lo[base + c] = l;
    }
}

// ---------------- HMMA GEMM: C[M,Nn] = A[M,K] @ W[Nn,K]^T ----------------
// 3-term bf16 split: Ah*Bh + Ah*Bl + Al*Bh  (fp32 accumulate)
// CFG 0: qkv   CFG 1: proj(+bias)  CFG 2: fc1(+bias,GELU,split out)  CFG 3: fc2(+bias,+res)
static constexpr int STAGE_BYTES = 65536;   // Ahi|Alo|Bhi|Blo 16KB each, xor-swizzled
static constexpr int SMEM_DYN = 2 * STAGE_BYTES;

template <int CFG>
__global__ void __launch_bounds__(256, 1)
gemm_mma(const float* __restrict__ bias, float* __restrict__ ext_out) {
    constexpr int Nn = (CFG == 0) ? C3 : (CFG == 2) ? DFF : C_;
    constexpr int K  = (CFG == 3) ? DFF : C_;
    constexpr int NC = K / 64;

    const __nv_bfloat16* Ahi = (CFG == 0 || CFG == 2) ? g_h_hi : (CFG == 1) ? g_at_hi : g_m_hi;
    const __nv_bfloat16* Alo = (CFG == 0 || CFG == 2) ? g_h_lo : (CFG == 1) ? g_at_lo : g_m_lo;
    const __nv_bfloat16* Whi = (CFG == 0) ? g_wq_hi : (CFG == 1) ? g_wp_hi : (CFG == 2) ? g_w1_hi : g_w2_hi;
    const __nv_bfloat16* Wlo = (CFG == 0) ? g_wq_lo : (CFG == 1) ? g_wp_lo : (CFG == 2) ? g_w1_lo : g_w2_lo;

    extern __shared__ char smraw[];
    uint32_t sbu = smem_u32(smraw);

    int tid = threadIdx.x, lane = tid & 31, wid = tid >> 5;
    int n0 = blockIdx.x * 128, m0 = blockIdx.y * 128;
    int wm0 = (wid & 3) * 32, wn0 = (wid >> 2) * 64;

    // issue one 64-wide K chunk into stage s
    auto issue = [&](int c, int s) {
        int k0 = c * 64;
        uint32_t sb = sbu + (uint32_t)s * STAGE_BYTES;
#pragma unroll
        for (int it = 0; it < 4; it++) {
            int idx = tid + it * 256;          // 0..1023
            int row = idx >> 3, unit = idx & 7;
            uint32_t soff = (uint32_t)row * 128u + (uint32_t)((unit ^ (row & 7)) << 4);
            int grA = m0 + row;
            int szA = (grA < BN) ? 16 : 0;
            const __nv_bfloat16* pa = Ahi + (size_t)grA * K + k0 + unit * 8;
            const __nv_bfloat16* pl = Alo + (size_t)grA * K + k0 + unit * 8;
            cp16(sb + soff,          pa, szA);
            cp16(sb + 16384 + soff,  pl, szA);
            const __nv_bfloat16* pb = Whi + (size_t)(n0 + row) * K + k0 + unit * 8;
            const __nv_bfloat16* pc = Wlo + (size_t)(n0 + row) * K + k0 + unit * 8;
            cp16(sb + 32768 + soff,  pb, 16);
            cp16(sb + 49152 + soff,  pc, 16);
        }
        cp_commit();
    };

    float d[2][8][4];
#pragma unroll
    for (int i = 0; i < 2; i++)
#pragma unroll
        for (int j = 0; j < 8; j++)
#pragma unroll
            for (int q = 0; q < 4; q++) d[i][j][q] = 0.f;

    issue(0, 0);
    for (int c = 0; c < NC; c++) {
        if (c + 1 < NC) { issue(c + 1, (c + 1) & 1); cp_wait<1>(); }
        else            { cp_wait<0>(); }
        __syncthreads();
        uint32_t sb = sbu + (uint32_t)(c & 1) * STAGE_BYTES;
#pragma unroll
        for (int kk = 0; kk < 4; kk++) {
            uint32_t ahi[2][4], alo[2][4];
#pragma unroll
            for (int mt = 0; mt < 2; mt++) {
                int row = wm0 + mt * 16 + (lane & 15);
                int unit = kk * 2 + (lane >> 4);
                uint32_t off = (uint32_t)row * 128u + (uint32_t)((unit ^ (row & 7)) << 4);
                ldm_x4(ahi[mt], sb + off);
                ldm_x4(alo[mt], sb + 16384 + off);
            }
            // B: W is [Nn, K] row-major == col-major B[k][n]; fragment needs
            // consecutive-k pairs at fixed n -> NON-transposed ldmatrix over n-rows.
            uint32_t bhi[4][4], blo[4][4];
#pragma unroll
            for (int ng = 0; ng < 4; ng++) {
                int row = wn0 + ng * 16 + (lane & 15);
                int unit = kk * 2 + (lane >> 4);
                uint32_t off = (uint32_t)row * 128u + (uint32_t)((unit ^ (row & 7)) << 4);
                ldm_x4(bhi[ng], sb + 32768 + off);
                ldm_x4(blo[ng], sb + 49152 + off);
            }
#pragma unroll
            for (int mt = 0; mt < 2; mt++)
#pragma unroll
                for (int ng = 0; ng < 4; ng++)
#pragma unroll
                    for (int hf = 0; hf < 2; hf++) {
                        int nt = ng * 2 + hf;
                        mma_bf16(d[mt][nt], ahi[mt], bhi[ng][hf], bhi[ng][hf + 2]);
                        mma_bf16(d[mt][nt], ahi[mt], blo[ng][hf], blo[ng][hf + 2]);
                        mma_bf16(d[mt][nt], alo[mt], bhi[ng][hf], bhi[ng][hf + 2]);
                    }
        }
        __syncthreads();
    }

    // epilogue: direct register -> global
#pragma unroll
    for (int mt = 0; mt < 2; mt++) {
#pragma unroll
        for (int half = 0; half < 2; half++) {
            int grow = m0 + wm0 + mt * 16 + (lane >> 2) + half * 8;
            if (grow >= BN) continue;
#pragma unroll
            for (int nt = 0; nt < 8; nt++) {
                int gc = n0 + wn0 + nt * 8 + (lane & 3) * 2;
                float v0 = d[mt][nt][half * 2 + 0];
                float v1 = d[mt][nt][half * 2 + 1];
                if constexpr (CFG == 0) {
                    *(float2*)&g_qkv[(size_t)grow * Nn + gc] = make_float2(v0, v1);
                } else if constexpr (CFG == 1) {
                    v0 += bias[gc]; v1 += bias[gc + 1];
                    *(float2*)&g_out[(size_t)grow * Nn + gc] = make_float2(v0, v1);
                } else if constexpr (CFG == 2) {
                    v0 += bias[gc]; v1 += bias[gc + 1];
                    v0 = 0.5f * v0 * (1.0f + erff(v0 * 0.70710678f));
                    v1 = 0.5f * v1 * (1.0f + erff(v1 * 0.70710678f));
                    __nv_bfloat16 h0, l0, h1, l1;
                    split_bf16(v0, h0, l0); split_bf16(v1, h1, l1);
                    size_t o = (size_t)grow * Nn + gc;
                    g_m_hi[o] = h0; g_m_hi[o + 1] = h1;
                    g_m_lo[o] = l0; g_m_lo[o + 1] = l1;
                } else {
                    size_t o = (size_t)grow * Nn + gc;
                    v0 += bias[gc]     + g_out[o];
                    v1 += bias[gc + 1] + g_out[o + 1];
                    *(float2*)&ext_out[o] = make_float2(v0, v1);
                }
            }
        }
    }
}

// ---------------- attention, spatial rows (i >= F): 9 keys each ----------------
__global__ void __launch_bounds__(256) attn_spatial() {
    const float* qkv = g_qkv;
    const int CH = (NTOK - F_) / 8;     // 195
    int bid   = blockIdx.x;
    int chunk = bid % CH;
    int bh    = bid / CH;
    int h     = bh % H_;
    int b     = bh / H_;

    __shared__ float ks[F_][D_], vs[F_][D_];
    int tid = threadIdx.x;
    for (int idx = tid; idx < F_ * D_; idx += 256) {
        int j = idx / D_, dd = idx % D_;
        const float* base = qkv + ((size_t)(b * NTOK + j)) * C3 + h * D_;
        ks[j][dd] = base[C_ + dd];
        vs[j][dd] = base[2 * C_ + dd];
    }
    __syncthreads();

    int warp = tid >> 5, lane = tid & 31;
    int i = F_ + chunk * 8 + warp;
    const float* q = qkv + ((size_t)(b * NTOK + i)) * C3 + h * D_;
    float q0 = q[lane], q1 = q[lane + 32];

    float lg[F_];
#pragma unroll
    for (int j = 0; j < F_; j++) {
        float p = q0 * ks[j][lane] + q1 * ks[j][lane + 32];
#pragma unroll
        for (int off = 16; off; off >>= 1) p += __shfl_xor_sync(0xffffffffu, p, off);
        lg[j] = p * 0.125f;
    }
    float m = lg[0];
#pragma unroll
    for (int j = 1; j < F_; j++) m = fmaxf(m, lg[j]);
    float s = 0.f, a0 = 0.f, a1 = 0.f;
#pragma unroll
    for (int j = 0; j < F_; j++) {
        float w = expf(lg[j] - m);
        s += w;
        a0 += w * vs[j][lane];
        a1 += w * vs[j][lane + 32];
    }
    float inv = 1.0f / s;
    size_t off0 = ((size_t)(b * NTOK + i)) * C_ + h * D_;
    __nv_bfloat16 h0, l0, h1, l1;
    split_bf16(a0 * inv, h0, l0);
    split_bf16(a1 * inv, h1, l1);
    g_at_hi[off0 + lane] = h0;       g_at_lo[off0 + lane] = l0;
    g_at_hi[off0 + lane + 32] = h1;  g_at_lo[off0 + lane + 32] = l1;
}

// ---------------- temporal rows: split-softmax partials ----------------
__global__ void __launch_bounds__(256) attn_tpart() {
    const float* qkv = g_qkv;
    int bid = blockIdx.x;
    int sp = bid % SPLIT;
    int t  = bid / SPLIT;
    int i = t % F_;
    int h = (t / F_) % H_;
    int b = t / (F_ * H_);

    __shared__ float qsh[D_];
    __shared__ float wm[8], ws[8];
    __shared__ float accs[8][D_];

    int tid = threadIdx.x, w = tid >> 5, lane = tid & 31;
    const float* q = qkv + ((size_t)(b * NTOK + i)) * C3 + h * D_;
    if (tid < D_) qsh[tid] = q[tid];
    __syncthreads();
    float q0 = qsh[lane], q1 = qsh[lane + 32];

    int cnt = (NTOK - F_) + (i == 0 ? 1 : 0);
    int g = sp * 8 + w;                  // global warp 0..63

    float mloc = -1e30f, sloc = 0.0f;
    for (int tt = g; tt < cnt; tt += SPLIT * 8) {
        int j = (i == 0) ? ((tt == 0) ? 0 : (F_ - 1 + tt)) : (F_ + tt);
        const float* kp = qkv + ((size_t)(b * NTOK + j)) * C3 + C_ + h * D_;
        float p = q0 * kp[lane] + q1 * kp[lane + 32];
#pragma unroll
        for (int off = 16; off; off >>= 1) p += __shfl_xor_sync(0xffffffffu, p, off);
        float lg = p * 0.125f;
        if (lg > mloc) { sloc *= expf(mloc - lg); mloc = lg; }
        sloc += expf(lg - mloc);
    }
    if (lane == 0) { wm[w] = mloc; ws[w] = sloc; }
    __syncthreads();
    float Mb = wm[0];
#pragma unroll
    for (int k = 1; k < 8; k++) Mb = fmaxf(Mb, wm[k]);
    float Sb = 0.f;
#pragma unroll
    for (int k = 0; k < 8; k++) Sb += ws[k] * expf(wm[k] - Mb);

    float a0 = 0.f, a1 = 0.f;
    for (int tt = g; tt < cnt; tt += SPLIT * 8) {
        int j = (i == 0) ? ((tt == 0) ? 0 : (F_ - 1 + tt)) : (F_ + tt);
        const float* kp = qkv + ((size_t)(b * NTOK + j)) * C3 + C_ + h * D_;
        float p = q0 * kp[lane] + q1 * kp[lane + 32];
#pragma unroll
        for (int off = 16; off; off >>= 1) p += __shfl_xor_sync(0xffffffffu, p, off);
        float w8 = expf(p * 0.125f - Mb);
        const float* vp = qkv + ((size_t)(b * NTOK + j)) * C3 + 2 * C_ + h * D_;
        a0 += w8 * vp[lane];
        a1 += w8 * vp[lane + 32];
    }
    accs[w][lane]      = a0;
    accs[w][lane + 32] = a1;
    __syncthreads();
    if (tid < D_) {
        float acc = 0.f;
#pragma unroll
        for (int k = 0; k < 8; k++) acc += accs[k][tid];
        float* pp = g_part + (size_t)(t * SPLIT + sp) * 66;
        pp[2 + tid] = acc;
        if (tid == 0) { pp[0] = Mb; pp[1] = Sb; }
    }
}

__global__ void __launch_bounds__(64) attn_tred() {
    int t = blockIdx.x;
    int i = t % F_;
    int h = (t / F_) % H_;
    int b = t / (F_ * H_);
    int d = threadIdx.x;

    float ms[SPLIT], ss[SPLIT];
    float M = -1e30f;
#pragma unroll
    for (int sp = 0; sp < SPLIT; sp++) {
        const float* pp = g_part + (size_t)(t * SPLIT + sp) * 66;
        ms[sp] = pp[0]; ss[sp] = pp[1];
        M = fmaxf(M, ms[sp]);
    }
    float S = 0.f, acc = 0.f;
#pragma unroll
    for (int sp = 0; sp < SPLIT; sp++) {
        float e = expf(ms[sp] - M);
        S += ss[sp] * e;
        acc += g_part[(size_t)(t * SPLIT + sp) * 66 + 2 + d] * e;
    }
    float v = acc / S;
    size_t off = ((size_t)(b * NTOK + i)) * C_ + h * D_ + d;
    __nv_bfloat16 hh, ll; split_bf16(v, hh, ll);
    g_at_hi[off] = hh; g_at_lo[off] = ll;
}

// ---------------- launch ----------------
extern "C" void kernel_launch(void* const* d_in, const int* in_sizes, int n_in,
                              void* d_out, int out_size) {
    const float* x     = (const float*)d_in[0];
    const float* ln_g  = (const float*)d_in[1];
    const float* ln_b  = (const float*)d_in[2];
    const float* qkvw  = (const float*)d_in[3];
    const float* projw = (const float*)d_in[4];
    const float* projb = (const float*)d_in[5];
    const float* fc1w  = (const float*)d_in[6];
    const float* fc1b  = (const float*)d_in[7];
    const float* fc2w  = (const float*)d_in[8];
    const float* fc2b  = (const float*)d_in[9];
    float* out = (float*)d_out;

    cudaFuncSetAttribute(gemm_mma<0>, cudaFuncAttributeMaxDynamicSharedMemorySize, SMEM_DYN);
    cudaFuncSetAttribute(gemm_mma<1>, cudaFuncAttributeMaxDynamicSharedMemorySize, SMEM_DYN);
    cudaFuncSetAttribute(gemm_mma<2>, cudaFuncAttributeMaxDynamicSharedMemorySize, SMEM_DYN);
    cudaFuncSetAttribute(gemm_mma<3>, cudaFuncAttributeMaxDynamicSharedMemorySize, SMEM_DYN);

    // weight splits (hi/lo bf16)
    cvt_kernel<0><<<(C3 * C_ + 255) / 256, 256>>>(qkvw, C3 * C_);
    cvt_kernel<1><<<(C_ * C_ + 255) / 256, 256>>>(projw, C_ * C_);
    cvt_kernel<2><<<(DFF * C_ + 255) / 256, 256>>>(fc1w, DFF * C_);
    cvt_kernel<3><<<(C_ * DFF + 255) / 256, 256>>>(fc2w, C_ * DFF);

    // 1. g_h = split(LN(x))
    ln_kernel<false><<<BN, 256>>>(x, ln_g, ln_b);

    // 2. g_qkv = g_h @ qkv_w^T
    gemm_mma<0><<<dim3(C3 / 128, (BN + 127) / 128), 256, SMEM_DYN>>>(nullptr, nullptr);

    // 3. masked attention -> g_at (hi/lo)
    attn_spatial<<<B_ * H_ * ((NTOK - F_) / 8), 256>>>();
    attn_tpart<<<B_ * H_ * F_ * SPLIT, 256>>>();
    attn_tred<<<B_ * H_ * F_, 64>>>();

    // 4. g_out = g_at @ proj_w^T + proj_b
    gemm_mma<1><<<dim3(C_ / 128, (BN + 127) / 128), 256, SMEM_DYN>>>(projb, nullptr);

    // 5. g_h = split(LN(g_out))
    ln_kernel<true><<<BN, 256>>>(nullptr, ln_g, ln_b);

    // 6. g_m = split(GELU(g_h @ fc1_w^T + fc1_b))
    gemm_mma<2><<<dim3(DFF / 128, (BN + 127) / 128), 256, SMEM_DYN>>>(fc1b, nullptr);

    // 7. d_out = g_out + g_m @ fc2_w^T + fc2_b
    gemm_mma<3><<<dim3(C_ / 128, (BN + 127) / 128), 256, SMEM_DYN>>>(fc2b, out);
}

// round 6
// speedup vs baseline: 2.8659x; 1.0049x over previous
#include <cuda_runtime.h>
#include <cuda_bf16.h>
#include <math.h>
#include <stdint.h>

// ---------------- problem constants ----------------
static constexpr int B_   = 4;
static constexpr int NTOK = 1569;
static constexpr int C_   = 768;
static constexpr int H_   = 12;
static constexpr int D_   = 64;
static constexpr int F_   = 9;            // CLS + 8 temporal tokens
static constexpr int BN   = B_ * NTOK;    // 6276
static constexpr int C3   = 3 * C_;       // 2304
static constexpr int DFF  = 4 * C_;       // 3072
static constexpr int SPLIT = 8;           // temporal-attention key split

// ---------------- scratch (device globals; no allocs) ----------------
__device__ __align__(16) float g_qkv[BN * C3];        // qkv projection (fp32)
__device__ __align__(16) float g_out[BN * C_];        // proj output ("new x", fp32)
__device__ __align__(16) __nv_bfloat16 g_h_hi[BN * C_],  g_h_lo[BN * C_];   // LN out
__device__ __align__(16) __nv_bfloat16 g_at_hi[BN * C_], g_at_lo[BN * C_];  // attn out
__device__ __align__(16) __nv_bfloat16 g_m_hi[BN * DFF], g_m_lo[BN * DFF];  // fc1 out
__device__ __align__(16) __nv_bfloat16 g_wq_hi[C3 * C_], g_wq_lo[C3 * C_];
__device__ __align__(16) __nv_bfloat16 g_wp_hi[C_ * C_], g_wp_lo[C_ * C_];
__device__ __align__(16) __nv_bfloat16 g_w1_hi[DFF * C_], g_w1_lo[DFF * C_];
__device__ __align__(16) __nv_bfloat16 g_w2_hi[C_ * DFF], g_w2_lo[C_ * DFF];
__device__ float g_part[B_ * H_ * F_ * SPLIT * 66];   // split-softmax partials

// ---------------- helpers ----------------
__device__ __forceinline__ uint32_t smem_u32(const void* p) {
    uint32_t a;
    asm("{ .reg .u64 t; cvta.to.shared.u64 t, %1; cvt.u32.u64 %0, t; }" : "=r"(a) : "l"(p));
    return a;
}
__device__ __forceinline__ void cp16(uint32_t dst, const void* src, int sz) {
    asm volatile("cp.async.cg.shared.global [%0], [%1], 16, %2;" :: "r"(dst), "l"(src), "r"(sz) : "memory");
}
__device__ __forceinline__ void cp_commit() { asm volatile("cp.async.commit_group;" ::: "memory"); }
template <int N>
__device__ __forceinline__ void cp_wait() { asm volatile("cp.async.wait_group %0;" :: "n"(N) : "memory"); }

__device__ __forceinline__ void ldm_x4(uint32_t* r, uint32_t addr) {
    asm volatile("ldmatrix.sync.aligned.m8n8.x4.shared.b16 {%0,%1,%2,%3}, [%4];"
                 : "=r"(r[0]), "=r"(r[1]), "=r"(r[2]), "=r"(r[3]) : "r"(addr));
}
__device__ __forceinline__ void mma_bf16(float* d, const uint32_t* a, uint32_t b0, uint32_t b1) {
    asm volatile("mma.sync.aligned.m16n8k16.row.col.f32.bf16.bf16.f32 "
                 "{%0,%1,%2,%3}, {%4,%5,%6,%7}, {%8,%9}, {%0,%1,%2,%3};"
                 : "+f"(d[0]), "+f"(d[1]), "+f"(d[2]), "+f"(d[3])
                 : "r"(a[0]), "r"(a[1]), "r"(a[2]), "r"(a[3]), "r"(b0), "r"(b1));
}

__device__ __forceinline__ void split_bf16(float v, __nv_bfloat16& hi, __nv_bfloat16& lo) {
    hi = __float2bfloat16(v);
    lo = __float2bfloat16(v - __bfloat162float(hi));
}

// ---------------- weight split kernels ----------------
template <int WID>
__global__ void __launch_bounds__(256) cvt_kernel(const float* __restrict__ w, int n) {
    __nv_bfloat16* hi; __nv_bfloat16* lo;
    if constexpr (WID == 0) { hi = g_wq_hi; lo = g_wq_lo; }
    else if constexpr (WID == 1) { hi = g_wp_hi; lo = g_wp_lo; }
    else if constexpr (WID == 2) { hi = g_w1_hi; lo = g_w1_lo; }
    else { hi = g_w2_hi; lo = g_w2_lo; }
    int i = blockIdx.x * 256 + threadIdx.x;
    if (i < n) { __nv_bfloat16 h, l; split_bf16(w[i], h, l); hi[i] = h; lo[i] = l; }
}

// ---------------- LayerNorm -> hi/lo bf16 into g_h ----------------
template <bool FROM_OUT>
__global__ void __launch_bounds__(256) ln_kernel(const float* __restrict__ ext_in,
                                                 const float* __restrict__ gam,
                                                 const float* __restrict__ bet) {
    const float* in = FROM_OUT ? g_out : ext_in;
    int row = blockIdx.x;
    const float* x = in + (size_t)row * C_;
    int tid = threadIdx.x;
    float v0 = x[tid], v1 = x[tid + 256], v2 = x[tid + 512];
    float s  = v0 + v1 + v2;
    float ss = v0 * v0 + v1 * v1 + v2 * v2;
#pragma unroll
    for (int off = 16; off; off >>= 1) {
        s  += __shfl_xor_sync(0xffffffffu, s, off);
        ss += __shfl_xor_sync(0xffffffffu, ss, off);
    }
    __shared__ float sm[8], sm2[8], stats[2];
    int warp = tid >> 5, lane = tid & 31;
    if (lane == 0) { sm[warp] = s; sm2[warp] = ss; }
    __syncthreads();
    if (tid == 0) {
        float S = 0.f, SS = 0.f;
#pragma unroll
        for (int w = 0; w < 8; w++) { S += sm[w]; SS += sm2[w]; }
        float mean = S * (1.0f / C_);
        float var  = SS * (1.0f / C_) - mean * mean;
        stats[0] = mean;
        stats[1] = rsqrtf(var + 1e-5f);
    }
    __syncthreads();
    float mean = stats[0], rstd = stats[1];
    size_t base = (size_t)row * C_;
#pragma unroll
    for (int t = 0; t < 3; t++) {
        int c = tid + t * 256;
        float v = t == 0 ? v0 : (t == 1 ? v1 : v2);
        float y = (v - mean) * rstd * gam[c] + bet[c];
        __nv_bfloat16 h, l; split_bf16(y, h, l);
        g_h_hi[base + c] = h; g_h_lo[base + c] = l;
    }
}

// ---------------- HMMA GEMM: C[M,Nn] = A[M,K] @ W[Nn,K]^T ----------------
// 3-term bf16 split: Ah*Bh + Ah*Bl + Al*Bh  (fp32 accumulate)
// 3-stage cp.async pipeline, one __syncthreads per chunk.
static constexpr int STAGES = 3;
static constexpr int STAGE_BYTES = 65536;   // Ahi|Alo|Bhi|Blo 16KB each, xor-swizzled
static constexpr int SMEM_DYN = STAGES * STAGE_BYTES;

template <int CFG>
__global__ void __launch_bounds__(256, 1)
gemm_mma(const float* __restrict__ bias, float* __restrict__ ext_out) {
    constexpr int Nn = (CFG == 0) ? C3 : (CFG == 2) ? DFF : C_;
    constexpr int K  = (CFG == 3) ? DFF : C_;
    constexpr int NC = K / 64;

    const __nv_bfloat16* Ahi = (CFG == 0 || CFG == 2) ? g_h_hi : (CFG == 1) ? g_at_hi : g_m_hi;
    const __nv_bfloat16* Alo = (CFG == 0 || CFG == 2) ? g_h_lo : (CFG == 1) ? g_at_lo : g_m_lo;
    const __nv_bfloat16* Whi = (CFG == 0) ? g_wq_hi : (CFG == 1) ? g_wp_hi : (CFG == 2) ? g_w1_hi : g_w2_hi;
    const __nv_bfloat16* Wlo = (CFG == 0) ? g_wq_lo : (CFG == 1) ? g_wp_lo : (CFG == 2) ? g_w1_lo : g_w2_lo;

    extern __shared__ char smraw[];
    uint32_t sbu = smem_u32(smraw);

    int tid = threadIdx.x, lane = tid & 31, wid = tid >> 5;
    int n0 = blockIdx.x * 128, m0 = blockIdx.y * 128;
    int wm0 = (wid & 3) * 32, wn0 = (wid >> 2) * 64;

    // issue one 64-wide K chunk into stage s
    auto issue = [&](int c, int s) {
        int k0 = c * 64;
        uint32_t sb = sbu + (uint32_t)s * STAGE_BYTES;
#pragma unroll
        for (int it = 0; it < 4; it++) {
            int idx = tid + it * 256;          // 0..1023
            int row = idx >> 3, unit = idx & 7;
            uint32_t soff = (uint32_t)row * 128u + (uint32_t)((unit ^ (row & 7)) << 4);
            int grA = m0 + row;
            int szA = (grA < BN) ? 16 : 0;
            const __nv_bfloat16* pa = Ahi + (size_t)grA * K + k0 + unit * 8;
            const __nv_bfloat16* pl = Alo + (size_t)grA * K + k0 + unit * 8;
            cp16(sb + soff,          pa, szA);
            cp16(sb + 16384 + soff,  pl, szA);
            const __nv_bfloat16* pb = Whi + (size_t)(n0 + row) * K + k0 + unit * 8;
            const __nv_bfloat16* pc = Wlo + (size_t)(n0 + row) * K + k0 + unit * 8;
            cp16(sb + 32768 + soff,  pb, 16);
            cp16(sb + 49152 + soff,  pc, 16);
        }
        cp_commit();
    };

    float d[2][8][4];
#pragma unroll
    for (int i = 0; i < 2; i++)
#pragma unroll
        for (int j = 0; j < 8; j++)
#pragma unroll
            for (int q = 0; q < 4; q++) d[i][j][q] = 0.f;

    issue(0, 0);
    issue(1, 1);
    for (int c = 0; c < NC; c++) {
        cp_wait<1>();
        __syncthreads();            // all threads see chunk c; stage (c+2)%3 free
        if (c + 2 < NC) issue(c + 2, (c + 2) % STAGES);
        uint32_t sb = sbu + (uint32_t)(c % STAGES) * STAGE_BYTES;
#pragma unroll
        for (int kk = 0; kk < 4; kk++) {
            uint32_t ahi[2][4], alo[2][4];
#pragma unroll
            for (int mt = 0; mt < 2; mt++) {
                int row = wm0 + mt * 16 + (lane & 15);
                int unit = kk * 2 + (lane >> 4);
                uint32_t off = (uint32_t)row * 128u + (uint32_t)((unit ^ (row & 7)) << 4);
                ldm_x4(ahi[mt], sb + off);
                ldm_x4(alo[mt], sb + 16384 + off);
            }
            // B: W is [Nn, K] row-major == col-major B[k][n]; fragment needs
            // consecutive-k pairs at fixed n -> NON-transposed ldmatrix over n-rows.
            uint32_t bhi[4][4], blo[4][4];
#pragma unroll
            for (int ng = 0; ng < 4; ng++) {
                int row = wn0 + ng * 16 + (lane & 15);
                int unit = kk * 2 + (lane >> 4);
                uint32_t off = (uint32_t)row * 128u + (uint32_t)((unit ^ (row & 7)) << 4);
                ldm_x4(bhi[ng], sb + 32768 + off);
                ldm_x4(blo[ng], sb + 49152 + off);
            }
#pragma unroll
            for (int mt = 0; mt < 2; mt++)
#pragma unroll
                for (int ng = 0; ng < 4; ng++)
#pragma unroll
                    for (int hf = 0; hf < 2; hf++) {
                        int nt = ng * 2 + hf;
                        mma_bf16(d[mt][nt], ahi[mt], bhi[ng][hf], bhi[ng][hf + 2]);
                        mma_bf16(d[mt][nt], ahi[mt], blo[ng][hf], blo[ng][hf + 2]);
                        mma_bf16(d[mt][nt], alo[mt], bhi[ng][hf], bhi[ng][hf + 2]);
                    }
        }
    }

    // epilogue: direct register -> global (registers only; no final sync needed)
#pragma unroll
    for (int mt = 0; mt < 2; mt++) {
#pragma unroll
        for (int half = 0; half < 2; half++) {
            int grow = m0 + wm0 + mt * 16 + (lane >> 2) + half * 8;
            if (grow >= BN) continue;
#pragma unroll
            for (int nt = 0; nt < 8; nt++) {
                int gc = n0 + wn0 + nt * 8 + (lane & 3) * 2;
                float v0 = d[mt][nt][half * 2 + 0];
                float v1 = d[mt][nt][half * 2 + 1];
                if constexpr (CFG == 0) {
                    *(float2*)&g_qkv[(size_t)grow * Nn + gc] = make_float2(v0, v1);
                } else if constexpr (CFG == 1) {
                    v0 += bias[gc]; v1 += bias[gc + 1];
                    *(float2*)&g_out[(size_t)grow * Nn + gc] = make_float2(v0, v1);
                } else if constexpr (CFG == 2) {
                    v0 += bias[gc]; v1 += bias[gc + 1];
                    v0 = 0.5f * v0 * (1.0f + erff(v0 * 0.70710678f));
                    v1 = 0.5f * v1 * (1.0f + erff(v1 * 0.70710678f));
                    __nv_bfloat16 h0, l0, h1, l1;
                    split_bf16(v0, h0, l0); split_bf16(v1, h1, l1);
                    size_t o = (size_t)grow * Nn + gc;
                    g_m_hi[o] = h0; g_m_hi[o + 1] = h1;
                    g_m_lo[o] = l0; g_m_lo[o + 1] = l1;
                } else {
                    size_t o = (size_t)grow * Nn + gc;
                    v0 += bias[gc]     + g_out[o];
                    v1 += bias[gc + 1] + g_out[o + 1];
                    *(float2*)&ext_out[o] = make_float2(v0, v1);
                }
            }
        }
    }
}

// ---------------- attention, spatial rows (i >= F): 9 keys each ----------------
__global__ void __launch_bounds__(256) attn_spatial() {
    const float* qkv = g_qkv;
    const int CH = (NTOK - F_) / 8;     // 195
    int bid   = blockIdx.x;
    int chunk = bid % CH;
    int bh    = bid / CH;
    int h     = bh % H_;
    int b     = bh / H_;

    __shared__ float ks[F_][D_], vs[F_][D_];
    int tid = threadIdx.x;
    for (int idx = tid; idx < F_ * D_; idx += 256) {
        int j = idx / D_, dd = idx % D_;
        const float* base = qkv + ((size_t)(b * NTOK + j)) * C3 + h * D_;
        ks[j][dd] = base[C_ + dd];
        vs[j][dd] = base[2 * C_ + dd];
    }
    __syncthreads();

    int warp = tid >> 5, lane = tid & 31;
    int i = F_ + chunk * 8 + warp;
    const float* q = qkv + ((size_t)(b * NTOK + i)) * C3 + h * D_;
    float q0 = q[lane], q1 = q[lane + 32];

    float lg[F_];
#pragma unroll
    for (int j = 0; j < F_; j++) {
        float p = q0 * ks[j][lane] + q1 * ks[j][lane + 32];
#pragma unroll
        for (int off = 16; off; off >>= 1) p += __shfl_xor_sync(0xffffffffu, p, off);
        lg[j] = p * 0.125f;
    }
    float m = lg[0];
#pragma unroll
    for (int j = 1; j < F_; j++) m = fmaxf(m, lg[j]);
    float s = 0.f, a0 = 0.f, a1 = 0.f;
#pragma unroll
    for (int j = 0; j < F_; j++) {
        float w = expf(lg[j] - m);
        s += w;
        a0 += w * vs[j][lane];
        a1 += w * vs[j][lane + 32];
    }
    float inv = 1.0f / s;
    size_t off0 = ((size_t)(b * NTOK + i)) * C_ + h * D_;
    __nv_bfloat16 h0, l0, h1, l1;
    split_bf16(a0 * inv, h0, l0);
    split_bf16(a1 * inv, h1, l1);
    g_at_hi[off0 + lane] = h0;       g_at_lo[off0 + lane] = l0;
    g_at_hi[off0 + lane + 32] = h1;  g_at_lo[off0 + lane + 32] = l1;
}

// ---------------- temporal rows: split-softmax partials ----------------
// pass 1 caches logits in smem; pass 2 reuses them (no K reload).
__global__ void __launch_bounds__(256) attn_tpart() {
    const float* qkv = g_qkv;
    int bid = blockIdx.x;
    int sp = bid % SPLIT;
    int t  = bid / SPLIT;
    int i = t % F_;
    int h = (t / F_) % H_;
    int b = t / (F_ * H_);

    __shared__ float qsh[D_];
    __shared__ float wm[8], ws[8];
    __shared__ float accs[8][D_];
    __shared__ float wlog[8][32];

    int tid = threadIdx.x, w = tid >> 5, lane = tid & 31;
    const float* q = qkv + ((size_t)(b * NTOK + i)) * C3 + h * D_;
    if (tid < D_) qsh[tid] = q[tid];
    __syncthreads();
    float q0 = qsh[lane], q1 = qsh[lane + 32];

    int cnt = (NTOK - F_) + (i == 0 ? 1 : 0);
    int g = sp * 8 + w;                  // global warp 0..63

    float mloc = -1e30f, sloc = 0.0f;
    int it = 0;
    for (int tt = g; tt < cnt; tt += SPLIT * 8, it++) {
        int j = (i == 0) ? ((tt == 0) ? 0 : (F_ - 1 + tt)) : (F_ + tt);
        const float* kp = qkv + ((size_t)(b * NTOK + j)) * C3 + C_ + h * D_;
        float p = q0 * kp[lane] + q1 * kp[lane + 32];
#pragma unroll
        for (int off = 16; off; off >>= 1) p += __shfl_xor_sync(0xffffffffu, p, off);
        float lg = p * 0.125f;
        if (lane == 0) wlog[w][it] = lg;
        if (lg > mloc) { sloc *= expf(mloc - lg); mloc = lg; }
        sloc += expf(lg - mloc);
    }
    if (lane == 0) { wm[w] = mloc; ws[w] = sloc; }
    __syncthreads();
    float Mb = wm[0];
#pragma unroll
    for (int k = 1; k < 8; k++) Mb = fmaxf(Mb, wm[k]);
    float Sb = 0.f;
#pragma unroll
    for (int k = 0; k < 8; k++) Sb += ws[k] * expf(wm[k] - Mb);

    float a0 = 0.f, a1 = 0.f;
    it = 0;
    for (int tt = g; tt < cnt; tt += SPLIT * 8, it++) {
        int j = (i == 0) ? ((tt == 0) ? 0 : (F_ - 1 + tt)) : (F_ + tt);
        float w8 = expf(wlog[w][it] - Mb);
        const float* vp = qkv + ((size_t)(b * NTOK + j)) * C3 + 2 * C_ + h * D_;
        a0 += w8 * vp[lane];
        a1 += w8 * vp[lane + 32];
    }
    accs[w][lane]      = a0;
    accs[w][lane + 32] = a1;
    __syncthreads();
    if (tid < D_) {
        float acc = 0.f;
#pragma unroll
        for (int k = 0; k < 8; k++) acc += accs[k][tid];
        float* pp = g_part + (size_t)(t * SPLIT + sp) * 66;
        pp[2 + tid] = acc;
        if (tid == 0) { pp[0] = Mb; pp[1] = Sb; }
    }
}

__global__ void __launch_bounds__(64) attn_tred() {
    int t = blockIdx.x;
    int i = t % F_;
    int h = (t / F_) % H_;
    int b = t / (F_ * H_);
    int d = threadIdx.x;

    float ms[SPLIT], ss[SPLIT];
    float M = -1e30f;
#pragma unroll
    for (int sp = 0; sp < SPLIT; sp++) {
        const float* pp = g_part + (size_t)(t * SPLIT + sp) * 66;
        ms[sp] = pp[0]; ss[sp] = pp[1];
        M = fmaxf(M, ms[sp]);
    }
    float S = 0.f, acc = 0.f;
#pragma unroll
    for (int sp = 0; sp < SPLIT; sp++) {
        float e = expf(ms[sp] - M);
        S += ss[sp] * e;
        acc += g_part[(size_t)(t * SPLIT + sp) * 66 + 2 + d] * e;
    }
    float v = acc / S;
    size_t off = ((size_t)(b * NTOK + i)) * C_ + h * D_ + d;
    __nv_bfloat16 hh, ll; split_bf16(v, hh, ll);
    g_at_hi[off] = hh; g_at_lo[off] = ll;
}

// ---------------- launch ----------------
extern "C" void kernel_launch(void* const* d_in, const int* in_sizes, int n_in,
                              void* d_out, int out_size) {
    const float* x     = (const float*)d_in[0];
    const float* ln_g  = (const float*)d_in[1];
    const float* ln_b  = (const float*)d_in[2];
    const float* qkvw  = (const float*)d_in[3];
    const float* projw = (const float*)d_in[4];
    const float* projb = (const float*)d_in[5];
    const float* fc1w  = (const float*)d_in[6];
    const float* fc1b  = (const float*)d_in[7];
    const float* fc2w  = (const float*)d_in[8];
    const float* fc2b  = (const float*)d_in[9];
    float* out = (float*)d_out;

    cudaFuncSetAttribute(gemm_mma<0>, cudaFuncAttributeMaxDynamicSharedMemorySize, SMEM_DYN);
    cudaFuncSetAttribute(gemm_mma<1>, cudaFuncAttributeMaxDynamicSharedMemorySize, SMEM_DYN);
    cudaFuncSetAttribute(gemm_mma<2>, cudaFuncAttributeMaxDynamicSharedMemorySize, SMEM_DYN);
    cudaFuncSetAttribute(gemm_mma<3>, cudaFuncAttributeMaxDynamicSharedMemorySize, SMEM_DYN);

    // weight splits (hi/lo bf16)
    cvt_kernel<0><<<(C3 * C_ + 255) / 256, 256>>>(qkvw, C3 * C_);
    cvt_kernel<1><<<(C_ * C_ + 255) / 256, 256>>>(projw, C_ * C_);
    cvt_kernel<2><<<(DFF * C_ + 255) / 256, 256>>>(fc1w, DFF * C_);
    cvt_kernel<3><<<(C_ * DFF + 255) / 256, 256>>>(fc2w, C_ * DFF);

    // 1. g_h = split(LN(x))
    ln_kernel<false><<<BN, 256>>>(x, ln_g, ln_b);

    // 2. g_qkv = g_h @ qkv_w^T
    gemm_mma<0><<<dim3(C3 / 128, (BN + 127) / 128), 256, SMEM_DYN>>>(nullptr, nullptr);

    // 3. masked attention -> g_at (hi/lo)
    attn_spatial<<<B_ * H_ * ((NTOK - F_) / 8), 256>>>();
    attn_tpart<<<B_ * H_ * F_ * SPLIT, 256>>>();
    attn_tred<<<B_ * H_ * F_, 64>>>();

    // 4. g_out = g_at @ proj_w^T + proj_b
    gemm_mma<1><<<dim3(C_ / 128, (BN + 127) / 128), 256, SMEM_DYN>>>(projb, nullptr);

    // 5. g_h = split(LN(g_out))
    ln_kernel<true><<<BN, 256>>>(nullptr, ln_g, ln_b);

    // 6. g_m = split(GELU(g_h @ fc1_w^T + fc1_b))
    gemm_mma<2><<<dim3(DFF / 128, (BN + 127) / 128), 256, SMEM_DYN>>>(fc1b, nullptr);

    // 7. d_out = g_out + g_m @ fc2_w^T + fc2_b
    gemm_mma<3><<<dim3(C_ / 128, (BN + 127) / 128), 256, SMEM_DYN>>>(fc2b, out);
}

// round 7
// speedup vs baseline: 4.3253x; 1.5092x over previous
#include <cuda_runtime.h>
#include <cuda_fp16.h>
#include <math.h>
#include <stdint.h>

// ---------------- problem constants ----------------
static constexpr int B_   = 4;
static constexpr int NTOK = 1569;
static constexpr int C_   = 768;
static constexpr int H_   = 12;
static constexpr int D_   = 64;
static constexpr int F_   = 9;            // CLS + 8 temporal tokens
static constexpr int BN   = B_ * NTOK;    // 6276
static constexpr int C3   = 3 * C_;       // 2304
static constexpr int DFF  = 4 * C_;       // 3072
static constexpr int SPLIT = 8;           // temporal-attention key split
static constexpr int NSP  = NTOK - F_;    // 1560 spatial keys

// ---------------- scratch (device globals; no allocs) ----------------
__device__ __align__(16) float g_qkv[BN * C3];        // qkv projection (fp32)
__device__ __align__(16) float g_out[BN * C_];        // proj output ("new x", fp32)
__device__ __align__(16) __half g_h[BN * C_];         // LN out (single fp16)
__device__ __align__(16) __half g_at[BN * C_];        // attn out (single fp16)
__device__ __align__(16) __half g_m[BN * DFF];        // fc1 out (single fp16)
__device__ __align__(16) __half g_wq_hi[C3 * C_], g_wq_lo[C3 * C_];
__device__ __align__(16) __half g_wp_hi[C_ * C_], g_wp_lo[C_ * C_];
__device__ __align__(16) __half g_w1_hi[DFF * C_], g_w1_lo[DFF * C_];
__device__ __align__(16) __half g_w2_hi[C_ * DFF], g_w2_lo[C_ * DFF];
__device__ float g_part[B_ * H_ * F_ * SPLIT * 66];   // split-softmax partials

// ---------------- helpers ----------------
__device__ __forceinline__ uint32_t smem_u32(const void* p) {
    uint32_t a;
    asm("{ .reg .u64 t; cvta.to.shared.u64 t, %1; cvt.u32.u64 %0, t; }" : "=r"(a) : "l"(p));
    return a;
}
__device__ __forceinline__ void cp16(uint32_t dst, const void* src, int sz) {
    asm volatile("cp.async.cg.shared.global [%0], [%1], 16, %2;" :: "r"(dst), "l"(src), "r"(sz) : "memory");
}
__device__ __forceinline__ void cp_commit() { asm volatile("cp.async.commit_group;" ::: "memory"); }
template <int N>
__device__ __forceinline__ void cp_wait() { asm volatile("cp.async.wait_group %0;" :: "n"(N) : "memory"); }

__device__ __forceinline__ void ldm_x4(uint32_t* r, uint32_t addr) {
    asm volatile("ldmatrix.sync.aligned.m8n8.x4.shared.b16 {%0,%1,%2,%3}, [%4];"
                 : "=r"(r[0]), "=r"(r[1]), "=r"(r[2]), "=r"(r[3]) : "r"(addr));
}
__device__ __forceinline__ void mma_f16(float* d, const uint32_t* a, uint32_t b0, uint32_t b1) {
    asm volatile("mma.sync.aligned.m16n8k16.row.col.f32.f16.f16.f32 "
                 "{%0,%1,%2,%3}, {%4,%5,%6,%7}, {%8,%9}, {%0,%1,%2,%3};"
                 : "+f"(d[0]), "+f"(d[1]), "+f"(d[2]), "+f"(d[3])
                 : "r"(a[0]), "r"(a[1]), "r"(a[2]), "r"(a[3]), "r"(b0), "r"(b1));
}

__device__ __forceinline__ void split_f16(float v, __half& hi, __half& lo) {
    hi = __float2half_rn(v);
    lo = __float2half_rn(v - __half2float(hi));
}

// ---------------- weight split kernels (fp16 hi/lo) ----------------
template <int WID>
__global__ void __launch_bounds__(256) cvt_kernel(const float* __restrict__ w, int n) {
    __half* hi; __half* lo;
    if constexpr (WID == 0) { hi = g_wq_hi; lo = g_wq_lo; }
    else if constexpr (WID == 1) { hi = g_wp_hi; lo = g_wp_lo; }
    else if constexpr (WID == 2) { hi = g_w1_hi; lo = g_w1_lo; }
    else { hi = g_w2_hi; lo = g_w2_lo; }
    int i = blockIdx.x * 256 + threadIdx.x;
    if (i < n) { __half h, l; split_f16(w[i], h, l); hi[i] = h; lo[i] = l; }
}

// ---------------- LayerNorm -> fp16 into g_h ----------------
template <bool FROM_OUT>
__global__ void __launch_bounds__(256) ln_kernel(const float* __restrict__ ext_in,
                                                 const float* __restrict__ gam,
                                                 const float* __restrict__ bet) {
    const float* in = FROM_OUT ? g_out : ext_in;
    int row = blockIdx.x;
    const float* x = in + (size_t)row * C_;
    int tid = threadIdx.x;
    float v0 = x[tid], v1 = x[tid + 256], v2 = x[tid + 512];
    float s  = v0 + v1 + v2;
    float ss = v0 * v0 + v1 * v1 + v2 * v2;
#pragma unroll
    for (int off = 16; off; off >>= 1) {
        s  += __shfl_xor_sync(0xffffffffu, s, off);
        ss += __shfl_xor_sync(0xffffffffu, ss, off);
    }
    __shared__ float sm[8], sm2[8], stats[2];
    int warp = tid >> 5, lane = tid & 31;
    if (lane == 0) { sm[warp] = s; sm2[warp] = ss; }
    __syncthreads();
    if (tid == 0) {
        float S = 0.f, SS = 0.f;
#pragma unroll
        for (int w = 0; w < 8; w++) { S += sm[w]; SS += sm2[w]; }
        float mean = S * (1.0f / C_);
        float var  = SS * (1.0f / C_) - mean * mean;
        stats[0] = mean;
        stats[1] = rsqrtf(var + 1e-5f);
    }
    __syncthreads();
    float mean = stats[0], rstd = stats[1];
    size_t base = (size_t)row * C_;
#pragma unroll
    for (int t = 0; t < 3; t++) {
        int c = tid + t * 256;
        float v = t == 0 ? v0 : (t == 1 ? v1 : v2);
        float y = (v - mean) * rstd * gam[c] + bet[c];
        g_h[base + c] = __float2half_rn(y);
    }
}

// ---------------- HMMA GEMM: C[M,Nn] = A[M,K] @ W[Nn,K]^T ----------------
// 2-term fp16: A (single fp16) x (Whi + Wlo), fp32 accumulate.
// CFG 0: qkv   CFG 1: proj(+bias)  CFG 2: fc1(+bias,GELU->fp16)  CFG 3: fc2(+bias,+res)
static constexpr int STAGE_BYTES = 49152;   // A 16KB | Bhi 16KB | Blo 16KB, xor-swizzled
static constexpr int SMEM_DYN = 2 * STAGE_BYTES;   // 96 KB -> 2 blocks/SM

template <int CFG>
__global__ void __launch_bounds__(256, 2)
gemm_mma(const float* __restrict__ bias, float* __restrict__ ext_out) {
    constexpr int Nn = (CFG == 0) ? C3 : (CFG == 2) ? DFF : C_;
    constexpr int K  = (CFG == 3) ? DFF : C_;
    constexpr int NC = K / 64;

    const __half* A   = (CFG == 0 || CFG == 2) ? g_h : (CFG == 1) ? g_at : g_m;
    const __half* Whi = (CFG == 0) ? g_wq_hi : (CFG == 1) ? g_wp_hi : (CFG == 2) ? g_w1_hi : g_w2_hi;
    const __half* Wlo = (CFG == 0) ? g_wq_lo : (CFG == 1) ? g_wp_lo : (CFG == 2) ? g_w1_lo : g_w2_lo;

    extern __shared__ char smraw[];
    uint32_t sbu = smem_u32(smraw);

    int tid = threadIdx.x, lane = tid & 31, wid = tid >> 5;
    int n0 = blockIdx.x * 128, m0 = blockIdx.y * 128;
    int wm0 = (wid & 3) * 32, wn0 = (wid >> 2) * 64;

    // issue one 64-wide K chunk into stage s
    auto issue = [&](int c, int s) {
        int k0 = c * 64;
        uint32_t sb = sbu + (uint32_t)s * STAGE_BYTES;
#pragma unroll
        for (int it = 0; it < 4; it++) {
            int idx = tid + it * 256;          // 0..1023
            int row = idx >> 3, unit = idx & 7;
            uint32_t soff = (uint32_t)row * 128u + (uint32_t)((unit ^ (row & 7)) << 4);
            int grA = m0 + row;
            int szA = (grA < BN) ? 16 : 0;
            cp16(sb + soff, A + (size_t)grA * K + k0 + unit * 8, szA);
            cp16(sb + 16384 + soff, Whi + (size_t)(n0 + row) * K + k0 + unit * 8, 16);
            cp16(sb + 32768 + soff, Wlo + (size_t)(n0 + row) * K + k0 + unit * 8, 16);
        }
        cp_commit();
    };

    float d[2][8][4];
#pragma unroll
    for (int i = 0; i < 2; i++)
#pragma unroll
        for (int j = 0; j < 8; j++)
#pragma unroll
            for (int q = 0; q < 4; q++) d[i][j][q] = 0.f;

    issue(0, 0);
    for (int c = 0; c < NC; c++) {
        if (c + 1 < NC) { issue(c + 1, (c + 1) & 1); cp_wait<1>(); }
        else            { cp_wait<0>(); }
        __syncthreads();
        uint32_t sb = sbu + (uint32_t)(c & 1) * STAGE_BYTES;
#pragma unroll
        for (int kk = 0; kk < 4; kk++) {
            uint32_t a[2][4];
#pragma unroll
            for (int mt = 0; mt < 2; mt++) {
                int row = wm0 + mt * 16 + (lane & 15);
                int unit = kk * 2 + (lane >> 4);
                uint32_t off = (uint32_t)row * 128u + (uint32_t)((unit ^ (row & 7)) << 4);
                ldm_x4(a[mt], sb + off);
            }
#pragma unroll
            for (int ng = 0; ng < 4; ng++) {
                int row = wn0 + ng * 16 + (lane & 15);
                int unit = kk * 2 + (lane >> 4);
                uint32_t off = (uint32_t)row * 128u + (uint32_t)((unit ^ (row & 7)) << 4);
                uint32_t bh4[4], bl4[4];
                ldm_x4(bh4, sb + 16384 + off);
                ldm_x4(bl4, sb + 32768 + off);
#pragma unroll
                for (int mt = 0; mt < 2; mt++)
#pragma unroll
                    for (int hf = 0; hf < 2; hf++) {
                        int nt = ng * 2 + hf;
                        mma_f16(d[mt][nt], a[mt], bh4[hf], bh4[hf + 2]);
                        mma_f16(d[mt][nt], a[mt], bl4[hf], bl4[hf + 2]);
                    }
            }
        }
        __syncthreads();
    }

    // epilogue: direct register -> global
#pragma unroll
    for (int mt = 0; mt < 2; mt++) {
#pragma unroll
        for (int half = 0; half < 2; half++) {
            int grow = m0 + wm0 + mt * 16 + (lane >> 2) + half * 8;
            if (grow >= BN) continue;
#pragma unroll
            for (int nt = 0; nt < 8; nt++) {
                int gc = n0 + wn0 + nt * 8 + (lane & 3) * 2;
                float v0 = d[mt][nt][half * 2 + 0];
                float v1 = d[mt][nt][half * 2 + 1];
                if constexpr (CFG == 0) {
                    *(float2*)&g_qkv[(size_t)grow * Nn + gc] = make_float2(v0, v1);
                } else if constexpr (CFG == 1) {
                    v0 += bias[gc]; v1 += bias[gc + 1];
                    *(float2*)&g_out[(size_t)grow * Nn + gc] = make_float2(v0, v1);
                } else if constexpr (CFG == 2) {
                    v0 += bias[gc]; v1 += bias[gc + 1];
                    v0 = 0.5f * v0 * (1.0f + erff(v0 * 0.70710678f));
                    v1 = 0.5f * v1 * (1.0f + erff(v1 * 0.70710678f));
                    size_t o = (size_t)grow * Nn + gc;
                    g_m[o]     = __float2half_rn(v0);
                    g_m[o + 1] = __float2half_rn(v1);
                } else {
                    size_t o = (size_t)grow * Nn + gc;
                    v0 += bias[gc]     + g_out[o];
                    v1 += bias[gc + 1] + g_out[o + 1];
                    *(float2*)&ext_out[o] = make_float2(v0, v1);
                }
            }
        }
    }
}

// ---------------- attention, spatial rows (i >= F): 9 keys each ----------------
__global__ void __launch_bounds__(256) attn_spatial() {
    const float* qkv = g_qkv;
    const int CH = NSP / 8;             // 195
    int bid   = blockIdx.x;
    int chunk = bid % CH;
    int bh    = bid / CH;
    int h     = bh % H_;
    int b     = bh / H_;

    __shared__ float ks[F_][D_], vs[F_][D_];
    int tid = threadIdx.x;
    for (int idx = tid; idx < F_ * D_; idx += 256) {
        int j = idx / D_, dd = idx % D_;
        const float* base = qkv + ((size_t)(b * NTOK + j)) * C3 + h * D_;
        ks[j][dd] = base[C_ + dd];
        vs[j][dd] = base[2 * C_ + dd];
    }
    __syncthreads();

    int warp = tid >> 5, lane = tid & 31;
    int i = F_ + chunk * 8 + warp;
    const float* q = qkv + ((size_t)(b * NTOK + i)) * C3 + h * D_;
    float q0 = q[lane], q1 = q[lane + 32];

    float lg[F_];
#pragma unroll
    for (int j = 0; j < F_; j++) {
        float p = q0 * ks[j][lane] + q1 * ks[j][lane + 32];
#pragma unroll
        for (int off = 16; off; off >>= 1) p += __shfl_xor_sync(0xffffffffu, p, off);
        lg[j] = p * 0.125f;
    }
    float m = lg[0];
#pragma unroll
    for (int j = 1; j < F_; j++) m = fmaxf(m, lg[j]);
    float s = 0.f, a0 = 0.f, a1 = 0.f;
#pragma unroll
    for (int j = 0; j < F_; j++) {
        float w = expf(lg[j] - m);
        s += w;
        a0 += w * vs[j][lane];
        a1 += w * vs[j][lane + 32];
    }
    float inv = 1.0f / s;
    size_t off0 = ((size_t)(b * NTOK + i)) * C_ + h * D_;
    g_at[off0 + lane]      = __float2half_rn(a0 * inv);
    g_at[off0 + lane + 32] = __float2half_rn(a1 * inv);
}

// ---------------- temporal rows: merged split-softmax partials ----------------
// one block per (b,h,sp); handles ALL 9 temporal rows; K/V read once.
__global__ void __launch_bounds__(256) attn_tpart() {
    const float* qkv = g_qkv;
    int bid = blockIdx.x;               // 0 .. B*H*SPLIT-1
    int sp = bid % SPLIT;
    int bh = bid / SPLIT;
    int h  = bh % H_;
    int b  = bh / H_;

    __shared__ float qsh[F_][D_];
    __shared__ float wm[8][F_], ws[8][F_];
    __shared__ float accs[8][F_][D_];
    __shared__ float wlog[8][25][F_];

    int tid = threadIdx.x, w = tid >> 5, lane = tid & 31;
    for (int idx = tid; idx < F_ * D_; idx += 256) {
        int i = idx / D_, dd = idx % D_;
        qsh[i][dd] = qkv[((size_t)(b * NTOK + i)) * C3 + h * D_ + dd];
    }
    __syncthreads();
    float q0[F_], q1[F_];
#pragma unroll
    for (int i = 0; i < F_; i++) { q0[i] = qsh[i][lane]; q1[i] = qsh[i][lane + 32]; }

    int g = sp * 8 + w;                 // global warp 0..63 strides the 1560 keys

    float m[F_], s[F_];
#pragma unroll
    for (int i = 0; i < F_; i++) { m[i] = -1e30f; s[i] = 0.f; }

    // pass 1: logits for all 9 rows per key; cache; online max/sum
    int it = 0;
    for (int tt = g; tt < NSP; tt += 64, it++) {
        const float* kp = qkv + ((size_t)(b * NTOK + F_ + tt)) * C3 + C_ + h * D_;
        float k0 = kp[lane], k1 = kp[lane + 32];
#pragma unroll
        for (int i = 0; i < F_; i++) {
            float p = q0[i] * k0 + q1[i] * k1;
#pragma unroll
            for (int off = 16; off; off >>= 1) p += __shfl_xor_sync(0xffffffffu, p, off);
            float lg = p * 0.125f;
            if (lane == 0) wlog[w][it][i] = lg;
            if (lg > m[i]) { s[i] *= expf(m[i] - lg); m[i] = lg; }
            s[i] += expf(lg - m[i]);
        }
    }
    // CLS key (j=0) contributes to row i=0 only; handled by global warp 0
    float clslog = 0.f;
    if (g == 0) {
        const float* kp = qkv + ((size_t)(b * NTOK + 0)) * C3 + C_ + h * D_;
        float p = q0[0] * kp[lane] + q1[0] * kp[lane + 32];
#pragma unroll
        for (int off = 16; off; off >>= 1) p += __shfl_xor_sync(0xffffffffu, p, off);
        clslog = p * 0.125f;
        if (clslog > m[0]) { s[0] *= expf(m[0] - clslog); m[0] = clslog; }
        s[0] += expf(clslog - m[0]);
    }
    if (lane == 0) {
#pragma unroll
        for (int i = 0; i < F_; i++) { wm[w][i] = m[i]; ws[w][i] = s[i]; }
    }
    __syncthreads();

    // block-level (per split) max/sum, computed redundantly by all threads
    float Mb[F_], Sb[F_];
#pragma unroll
    for (int i = 0; i < F_; i++) {
        float M = wm[0][i];
#pragma unroll
        for (int k = 1; k < 8; k++) M = fmaxf(M, wm[k][i]);
        float S = 0.f;
#pragma unroll
        for (int k = 0; k < 8; k++) S += ws[k][i] * expf(wm[k][i] - M);
        Mb[i] = M; Sb[i] = S;
    }

    // pass 2: V accumulation with cached logits
    float a0[F_], a1[F_];
#pragma unroll
    for (int i = 0; i < F_; i++) { a0[i] = 0.f; a1[i] = 0.f; }
    it = 0;
    for (int tt = g; tt < NSP; tt += 64, it++) {
        const float* vp = qkv + ((size_t)(b * NTOK + F_ + tt)) * C3 + 2 * C_ + h * D_;
        float v0 = vp[lane], v1 = vp[lane + 32];
#pragma unroll
        for (int i = 0; i < F_; i++) {
            float w8 = expf(wlog[w][it][i] - Mb[i]);
            a0[i] += w8 * v0;
            a1[i] += w8 * v1;
        }
    }
    if (g == 0) {
        const float* vp = qkv + ((size_t)(b * NTOK + 0)) * C3 + 2 * C_ + h * D_;
        float w8 = expf(clslog - Mb[0]);
        a0[0] += w8 * vp[lane];
        a1[0] += w8 * vp[lane + 32];
    }
#pragma unroll
    for (int i = 0; i < F_; i++) {
        accs[w][i][lane]      = a0[i];
        accs[w][i][lane + 32] = a1[i];
    }
    __syncthreads();

    for (int idx = tid; idx < F_ * D_; idx += 256) {
        int i = idx / D_, dd = idx % D_;
        float acc = 0.f;
#pragma unroll
        for (int k = 0; k < 8; k++) acc += accs[k][i][dd];
        float* pp = g_part + (size_t)(((bh * F_ + i) * SPLIT) + sp) * 66;
        pp[2 + dd] = acc;
        if (dd == 0) { pp[0] = Mb[i]; pp[1] = Sb[i]; }
    }
}

__global__ void __launch_bounds__(64) attn_tred() {
    int t = blockIdx.x;                 // 0 .. B*H*F-1  (t = bh*F + i)
    int i  = t % F_;
    int bh = t / F_;
    int h = bh % H_;
    int b = bh / H_;
    int d = threadIdx.x;

    float ms[SPLIT], ss[SPLIT];
    float M = -1e30f;
#pragma unroll
    for (int sp = 0; sp < SPLIT; sp++) {
        const float* pp = g_part + (size_t)(t * SPLIT + sp) * 66;
        ms[sp] = pp[0]; ss[sp] = pp[1];
        M = fmaxf(M, ms[sp]);
    }
    float S = 0.f, acc = 0.f;
#pragma unroll
    for (int sp = 0; sp < SPLIT; sp++) {
        float e = expf(ms[sp] - M);
        S += ss[sp] * e;
        acc += g_part[(size_t)(t * SPLIT + sp) * 66 + 2 + d] * e;
    }
    g_at[((size_t)(b * NTOK + i)) * C_ + h * D_ + d] = __float2half_rn(acc / S);
}

// ---------------- launch ----------------
extern "C" void kernel_launch(void* const* d_in, const int* in_sizes, int n_in,
                              void* d_out, int out_size) {
    const float* x     = (const float*)d_in[0];
    const float* ln_g  = (const float*)d_in[1];
    const float* ln_b  = (const float*)d_in[2];
    const float* qkvw  = (const float*)d_in[3];
    const float* projw = (const float*)d_in[4];
    const float* projb = (const float*)d_in[5];
    const float* fc1w  = (const float*)d_in[6];
    const float* fc1b  = (const float*)d_in[7];
    const float* fc2w  = (const float*)d_in[8];
    const float* fc2b  = (const float*)d_in[9];
    float* out = (float*)d_out;

    cudaFuncSetAttribute(gemm_mma<0>, cudaFuncAttributeMaxDynamicSharedMemorySize, SMEM_DYN);
    cudaFuncSetAttribute(gemm_mma<1>, cudaFuncAttributeMaxDynamicSharedMemorySize, SMEM_DYN);
    cudaFuncSetAttribute(gemm_mma<2>, cudaFuncAttributeMaxDynamicSharedMemorySize, SMEM_DYN);
    cudaFuncSetAttribute(gemm_mma<3>, cudaFuncAttributeMaxDynamicSharedMemorySize, SMEM_DYN);

    // weight splits (fp16 hi/lo)
    cvt_kernel<0><<<(C3 * C_ + 255) / 256, 256>>>(qkvw, C3 * C_);
    cvt_kernel<1><<<(C_ * C_ + 255) / 256, 256>>>(projw, C_ * C_);
    cvt_kernel<2><<<(DFF * C_ + 255) / 256, 256>>>(fc1w, DFF * C_);
    cvt_kernel<3><<<(C_ * DFF + 255) / 256, 256>>>(fc2w, C_ * DFF);

    // 1. g_h = fp16(LN(x))
    ln_kernel<false><<<BN, 256>>>(x, ln_g, ln_b);

    // 2. g_qkv = g_h @ qkv_w^T
    gemm_mma<0><<<dim3(C3 / 128, (BN + 127) / 128), 256, SMEM_DYN>>>(nullptr, nullptr);

    // 3. masked attention -> g_at (fp16)
    attn_spatial<<<B_ * H_ * (NSP / 8), 256>>>();
    attn_tpart<<<B_ * H_ * SPLIT, 256>>>();
    attn_tred<<<B_ * H_ * F_, 64>>>();

    // 4. g_out = g_at @ proj_w^T + proj_b
    gemm_mma<1><<<dim3(C_ / 128, (BN + 127) / 128), 256, SMEM_DYN>>>(projb, nullptr);

    // 5. g_h = fp16(LN(g_out))
    ln_kernel<true><<<BN, 256>>>(nullptr, ln_g, ln_b);

    // 6. g_m = fp16(GELU(g_h @ fc1_w^T + fc1_b))
    gemm_mma<2><<<dim3(DFF / 128, (BN + 127) / 128), 256, SMEM_DYN>>>(fc1b, nullptr);

    // 7. d_out = g_out + g_m @ fc2_w^T + fc2_b
    gemm_mma<3><<<dim3(C_ / 128, (BN + 127) / 128), 256, SMEM_DYN>>>(fc2b, out);
}